// round 1
// baseline (speedup 1.0000x reference)
#include <cuda_runtime.h>

#define BATCH 262144

// ---- scratch (static __device__ arrays: the sanctioned no-alloc path) ----
__device__ float g_h0[BATCH * 256];
__device__ float g_h1[BATCH * 256];
__device__ float g_wt[4 * 256 * 64];   // prepped weights for current layer: [kO][i][v]
__device__ float g_bias[256];          // prepped (summed) bias for current layer: [kO][v]
__device__ float g_sumsq[32];          // slots: 0..3 layer sumsq (4 nodes each), slot4[0]=out

// ------------------------------------------------------------------
__global__ void zero_kernel() {
    if (threadIdx.x < 32) g_sumsq[threadIdx.x] = 0.0f;
}

// input layer weights: g_wt[kO*4096 + w*64 + v] = W_in[kO][v][w]
__global__ void prep_in(const float* __restrict__ W, const float* __restrict__ b) {
    int e = blockIdx.x * 256 + threadIdx.x;            // 16384
    int kO = e >> 12, w = (e >> 6) & 63, v = e & 63;
    g_wt[e] = W[(kO << 12) + (v << 6) + w];
    if (e < 256) g_bias[e] = b[e];
}

// mid layer l: g_wt[kO*16384 + (p*64+w)*64 + v] = W_mid[l][p][kO][v][w] * rsqrt(sumsq[slot_in][p])
__global__ void prep_mid(const float* __restrict__ W, const float* __restrict__ b,
                         int l, int slot_in) {
    int e = blockIdx.x * 256 + threadIdx.x;            // 65536
    int kO = e >> 14, i = (e >> 6) & 255, v = e & 63;
    int p = i >> 6, w = i & 63;
    float s = rsqrtf(g_sumsq[(slot_in << 2) + p]);
    g_wt[e] = W[(((l * 4 + p) * 4 + kO) << 12) + (v << 6) + w] * s;
    if (e < 256) {
        int kk = e >> 6, vv = e & 63;
        float bs = 0.f;
        #pragma unroll
        for (int p2 = 0; p2 < 4; p2++)
            bs += b[(((l * 4 + p2) * 4 + kk) << 6) + vv];
        g_bias[e] = bs;
    }
}

// out layer: g_wt[(p*64+w)*64 + v] = W_out[p][v][w] * rsqrt(sumsq[slot_in][p])
__global__ void prep_out(const float* __restrict__ W, const float* __restrict__ b,
                         int slot_in) {
    int e = blockIdx.x * 256 + threadIdx.x;            // 16384
    int i = e >> 6, v = e & 63;
    int p = i >> 6, w = i & 63;
    float s = rsqrtf(g_sumsq[(slot_in << 2) + p]);
    g_wt[e] = W[(p << 12) + (v << 6) + w] * s;
    if (e < 64) {
        float bs = 0.f;
        #pragma unroll
        for (int p2 = 0; p2 < 4; p2++)
            bs += b[(p2 << 6) + e];
        g_bias[e] = bs;
    }
}

// ------------------------------------------------------------------
// GEMM: Y[b, kO*64+v] = sum_i A[b,i] * g_wt[kO][i][v] + g_bias[kO][v]
// block = 256 threads, tile BM=128 x BN=64 (one output node), TM=4 x TN=8.
#define SM_WS 68
#define SM_AS 66
#define SMEM_FLOATS (64 * SM_WS + 128 * SM_AS + 64 + 256)

template <int KDIM>
__global__ void __launch_bounds__(256) gemm_kernel(
        const float* __restrict__ A_ext, float* __restrict__ Y_ext,
        int abuf, int ybuf, int ldY, int slot_out)
{
    const float* A = (abuf == 0) ? g_h0 : (abuf == 1) ? g_h1 : A_ext;
    float* Y       = (ybuf == 0) ? g_h0 : (ybuf == 1) ? g_h1 : Y_ext;
    const int kO   = blockIdx.y;
    const int row0 = blockIdx.x << 7;
    const int tid  = threadIdx.x;

    extern __shared__ float sm[];
    float* wsh = sm;                        // [64][68]  weights chunk (i-row, v-col)
    float* ash = sm + 64 * SM_WS;           // [128][66] A tile (row, k-col)
    float* bsh = ash + 128 * SM_AS;         // [64]
    float* red = bsh + 64;                  // [256]

    if (tid < 64) bsh[tid] = g_bias[(kO << 6) + tid];

    const int cg = (tid & 7) << 3;          // TN=8 column base
    const int rg = (tid >> 3) << 2;         // TM=4 row base

    float acc[4][8];
    #pragma unroll
    for (int m = 0; m < 4; m++)
        #pragma unroll
        for (int n = 0; n < 8; n++) acc[m][n] = 0.f;

    const float* Wk = g_wt + kO * (KDIM * 64);

    for (int kk = 0; kk < KDIM; kk += 64) {
        __syncthreads();
        // weights chunk: straight float4 copy (prep kernel already transposed+scaled)
        #pragma unroll
        for (int e = tid; e < 64 * 16; e += 256) {
            int i = e >> 4, v4 = (e & 15) << 2;
            *(float4*)(wsh + i * SM_WS + v4) =
                *(const float4*)(Wk + ((kk + i) << 6) + v4);
        }
        // A tile: float4 global load, float2 smem stores (stride 66 keeps reads conflict-free)
        #pragma unroll
        for (int e = tid; e < 128 * 16; e += 256) {
            int r = e >> 4, c4 = (e & 15) << 2;
            float4 av = *(const float4*)(A + (size_t)(row0 + r) * KDIM + kk + c4);
            float* dst = ash + r * SM_AS + c4;
            *(float2*)dst       = make_float2(av.x, av.y);
            *(float2*)(dst + 2) = make_float2(av.z, av.w);
        }
        __syncthreads();

        const float* ar = ash + rg * SM_AS;
        #pragma unroll 8
        for (int k = 0; k < 64; k++) {
            float aa[4];
            aa[0] = ar[k];
            aa[1] = ar[SM_AS + k];
            aa[2] = ar[2 * SM_AS + k];
            aa[3] = ar[3 * SM_AS + k];
            float4 b0 = *(const float4*)(wsh + k * SM_WS + cg);
            float4 b1 = *(const float4*)(wsh + k * SM_WS + cg + 4);
            float bb[8] = {b0.x, b0.y, b0.z, b0.w, b1.x, b1.y, b1.z, b1.w};
            #pragma unroll
            for (int m = 0; m < 4; m++)
                #pragma unroll
                for (int n = 0; n < 8; n++)
                    acc[m][n] += aa[m] * bb[n];
        }
    }

    // epilogue: bias add, store, per-node sumsq
    float lsq = 0.f;
    #pragma unroll
    for (int m = 0; m < 4; m++) {
        int row = row0 + rg + m;
        float o[8];
        #pragma unroll
        for (int n = 0; n < 8; n++) {
            o[n] = acc[m][n] + bsh[cg + n];
            lsq += o[n] * o[n];
        }
        float* yp = Y + (size_t)row * ldY + (kO << 6) + cg;
        *(float4*)yp       = make_float4(o[0], o[1], o[2], o[3]);
        *(float4*)(yp + 4) = make_float4(o[4], o[5], o[6], o[7]);
    }

    red[tid] = lsq;
    __syncthreads();
    #pragma unroll
    for (int s = 128; s > 0; s >>= 1) {
        if (tid < s) red[tid] += red[tid + s];
        __syncthreads();
    }
    if (tid == 0) atomicAdd(&g_sumsq[(slot_out << 2) + kO], red[0]);
}

// ------------------------------------------------------------------
__global__ void finalize_kernel(float* __restrict__ out) {
    float s = rsqrtf(g_sumsq[16]);
    int i = blockIdx.x * blockDim.x + threadIdx.x;   // 4,194,304 float4
    float4* o = (float4*)out;
    float4 v = o[i];
    v.x *= s; v.y *= s; v.z *= s; v.w *= s;
    o[i] = v;
}

// ------------------------------------------------------------------
extern "C" void kernel_launch(void* const* d_in, const int* in_sizes, int n_in,
                              void* d_out, int out_size)
{
    const float* x     = (const float*)d_in[0];
    const float* W_in  = (const float*)d_in[1];
    const float* b_in  = (const float*)d_in[2];
    const float* W_mid = (const float*)d_in[3];
    const float* b_mid = (const float*)d_in[4];
    const float* W_out = (const float*)d_in[5];
    const float* b_out = (const float*)d_in[6];
    float* out = (float*)d_out;

    const int SMEM = SMEM_FLOATS * 4;   // 52480 bytes
    cudaFuncSetAttribute(gemm_kernel<64>,  cudaFuncAttributeMaxDynamicSharedMemorySize, SMEM);
    cudaFuncSetAttribute(gemm_kernel<256>, cudaFuncAttributeMaxDynamicSharedMemorySize, SMEM);

    zero_kernel<<<1, 32>>>();

    // input layer: x [B,64] -> h0 [B,256], sumsq slot 0
    prep_in<<<64, 256>>>(W_in, b_in);
    gemm_kernel<64><<<dim3(2048, 4), 256, SMEM>>>(x, nullptr, -1, 0, 256, 0);

    // 3 mid transitions (scale folded into weights by prep from previous slot)
    int a = 0;
    for (int l = 0; l < 3; l++) {
        prep_mid<<<256, 256>>>(W_mid, b_mid, l, l);
        gemm_kernel<256><<<dim3(2048, 4), 256, SMEM>>>(nullptr, nullptr, a, 1 - a, 256, l + 1);
        a = 1 - a;
    }

    // output layer -> d_out raw, sumsq slot 4; then normalize in place
    prep_out<<<64, 256>>>(W_out, b_out, 3);
    gemm_kernel<256><<<dim3(2048, 1), 256, SMEM>>>(nullptr, out, a, -1, 64, 4);
    finalize_kernel<<<16384, 256>>>(out);
}

// round 4
// speedup vs baseline: 8.3098x; 8.3098x over previous
#include <cuda_runtime.h>
#include <cuda_bf16.h>
#include <cstdint>

#define BATCH 262144

// ---------------- scratch (__device__ globals: the sanctioned no-alloc path) ---
__device__ __nv_bfloat16 g_xb[BATCH * 64];      // x converted to bf16
__device__ __nv_bfloat16 g_hb0[BATCH * 256];    // activations ping
__device__ __nv_bfloat16 g_hb1[BATCH * 256];    // activations pong
__device__ __nv_bfloat16 g_wt[256 * 256];       // prepped W^T bf16: [n][k]
__device__ float g_bias[256];                   // summed bias (fp32), current layer
__device__ float g_sumsq[32];                   // slots 0..3 per-node; [16] output

// ---------------- helpers -----------------------------------------------------
__device__ __forceinline__ uint32_t smem_u32(const void* p) {
    uint32_t a;
    asm("{ .reg .u64 t; cvta.to.shared.u64 t, %1; cvt.u32.u64 %0, t; }" : "=r"(a) : "l"(p));
    return a;
}
__device__ __forceinline__ uint32_t sw128(uint32_t off) {
    return off ^ ((off >> 3) & 0x70);
}
__device__ __forceinline__ void cp16(uint32_t s, const void* g) {
    asm volatile("cp.async.cg.shared.global [%0], [%1], 16;" :: "r"(s), "l"(g));
}
__device__ __forceinline__ void ldm_x4(uint32_t* r, uint32_t addr) {
    asm volatile("ldmatrix.sync.aligned.m8n8.x4.shared.b16 {%0,%1,%2,%3}, [%4];"
                 : "=r"(r[0]), "=r"(r[1]), "=r"(r[2]), "=r"(r[3]) : "r"(addr));
}
__device__ __forceinline__ void mma16816(float* d, const uint32_t* a, const uint32_t* b) {
    asm volatile(
        "mma.sync.aligned.m16n8k16.row.col.f32.bf16.bf16.f32 "
        "{%0,%1,%2,%3}, {%4,%5,%6,%7}, {%8,%9}, {%0,%1,%2,%3};"
        : "+f"(d[0]), "+f"(d[1]), "+f"(d[2]), "+f"(d[3])
        : "r"(a[0]), "r"(a[1]), "r"(a[2]), "r"(a[3]), "r"(b[0]), "r"(b[1]));
}

// ---------------- tiny prep kernels -------------------------------------------
__global__ void zero_kernel() { if (threadIdx.x < 32) g_sumsq[threadIdx.x] = 0.f; }

__global__ void convert_x(const float* __restrict__ x) {
    int i = blockIdx.x * 256 + threadIdx.x;                // 4,194,304 float4s
    float4 v = ((const float4*)x)[i];
    __nv_bfloat162* o = (__nv_bfloat162*)g_xb;
    o[2 * i]     = __floats2bfloat162_rn(v.x, v.y);
    o[2 * i + 1] = __floats2bfloat162_rn(v.z, v.w);
}

// g_wt[j*64 + w] = W_in[kO][v][w], j = kO*64+v
__global__ void prep_in(const float* __restrict__ W, const float* __restrict__ b) {
    int e = blockIdx.x * 256 + threadIdx.x;                // 16384
    int j = e >> 6, w = e & 63;
    g_wt[e] = __float2bfloat16(W[((j >> 6) << 12) + ((j & 63) << 6) + w]);
    if (e < 256) g_bias[e] = b[e];
}

// g_wt[j*256 + p*64+w] = W_mid[l][p][kO][v][w] * rsqrt(ss[p]) ; j=kO*64+v
__global__ void prep_mid(const float* __restrict__ W, const float* __restrict__ b,
                         int l, int slot_in) {
    int e = blockIdx.x * 256 + threadIdx.x;                // 65536
    int j = e >> 8, i = e & 255;
    int kO = j >> 6, v = j & 63, p = i >> 6, w = i & 63;
    float s = rsqrtf(g_sumsq[(slot_in << 2) + p]);
    g_wt[e] = __float2bfloat16(W[(((l * 4 + p) * 4 + kO) << 12) + (v << 6) + w] * s);
    if (e < 256) {
        int kk = e >> 6, vv = e & 63;
        float bs = 0.f;
        #pragma unroll
        for (int p2 = 0; p2 < 4; p2++) bs += b[(((l * 4 + p2) * 4 + kk) << 6) + vv];
        g_bias[e] = bs;
    }
}

// g_wt[v*256 + p*64+w] = W_out[p][v][w] * rsqrt(ss[p])
__global__ void prep_out(const float* __restrict__ W, const float* __restrict__ b,
                         int slot_in) {
    int e = blockIdx.x * 256 + threadIdx.x;                // 16384
    int v = e >> 8, i = e & 255, p = i >> 6, w = i & 63;
    float s = rsqrtf(g_sumsq[(slot_in << 2) + p]);
    g_wt[e] = __float2bfloat16(W[(p << 12) + (v << 6) + w] * s);
    if (e < 64) {
        float bs = 0.f;
        #pragma unroll
        for (int p2 = 0; p2 < 4; p2++) bs += b[(p2 << 6) + e];
        g_bias[e] = bs;
    }
}

// ---------------- bf16 HMMA GEMM ----------------------------------------------
// C[row0+0..127, n0..n0+BN) = A[.,0..K) @ Wt^T (+bias, per-node sumsq)
// A bf16 [B,K] row-major; Wt bf16 [n][k]. BK=64 chunks, SW128 smem, cp.async x2.
template <int K, int BN, bool OUTF32>
__global__ void __launch_bounds__(256, 2) mma_gemm(
        int asel, int ysel, float* __restrict__ Yf, int ldY, int slot_out)
{
    constexpr int NCH    = K / 64;
    constexpr int ABYTES = 128 * 128;            // 16 KB
    constexpr int BBYTES = BN * 128;
    constexpr int STAGE  = ABYTES + BBYTES;
    constexpr int NWN    = (BN == 128) ? 4 : 2;  // warps along N
    constexpr int NWM    = 8 / NWN;
    constexpr int WM     = 128 / NWM;            // 64 or 32
    constexpr int MI     = WM / 16;              // 4 or 2

    extern __shared__ char smem[];
    __shared__ float s_bias[BN];

    const __nv_bfloat16* A = (asel == 0) ? g_xb : (asel == 1) ? g_hb0 : g_hb1;
    __nv_bfloat16* Yb      = (ysel == 1) ? g_hb0 : g_hb1;

    const int tid  = threadIdx.x;
    const int wid  = tid >> 5, lane = tid & 31;
    const int row0 = blockIdx.x << 7;
    const int n0   = blockIdx.y * BN;
    const int wm   = (wid / NWN) * WM;
    const int wn   = (wid % NWN) * 32;

    if (tid < BN) s_bias[tid] = g_bias[n0 + tid];

    const uint32_t smb = smem_u32(smem);

    auto load_chunk = [&](int c, int st) {
        uint32_t sA = smb + st * STAGE;
        uint32_t sB = sA + ABYTES;
        #pragma unroll
        for (int i = 0; i < 4; i++) {                    // A: 1024 x 16B
            int e = tid + i * 256, r = e >> 3, q = e & 7;
            cp16(sA + sw128((r << 7) + (q << 4)),
                 A + (size_t)(row0 + r) * K + c * 64 + q * 8);
        }
        #pragma unroll
        for (int i = 0; i < BN * 8 / 256; i++) {         // B: BN*8 x 16B
            int e = tid + i * 256, n = e >> 3, q = e & 7;
            cp16(sB + sw128((n << 7) + (q << 4)),
                 g_wt + (size_t)(n0 + n) * K + c * 64 + q * 8);
        }
        asm volatile("cp.async.commit_group;" ::: "memory");
    };

    float acc[MI][4][4];
    #pragma unroll
    for (int m = 0; m < MI; m++)
        #pragma unroll
        for (int n = 0; n < 4; n++)
            #pragma unroll
            for (int r = 0; r < 4; r++) acc[m][n][r] = 0.f;

    const int g = lane >> 3, rin = lane & 7;

    load_chunk(0, 0);

    for (int c = 0; c < NCH; c++) {
        if (c + 1 < NCH) {
            load_chunk(c + 1, (c + 1) & 1);
            asm volatile("cp.async.wait_group 1;" ::: "memory");
        } else {
            asm volatile("cp.async.wait_group 0;" ::: "memory");
        }
        __syncthreads();

        const uint32_t sA = smb + (c & 1) * STAGE;
        const uint32_t sB = sA + ABYTES;
        #pragma unroll
        for (int k16 = 0; k16 < 4; k16++) {
            uint32_t af[MI][4];
            #pragma unroll
            for (int mi = 0; mi < MI; mi++) {
                int row = wm + mi * 16 + ((g & 1) << 3) + rin;
                ldm_x4(af[mi], sA + sw128((row << 7) + k16 * 32 + ((g >> 1) << 4)));
            }
            uint32_t bf[4][2];
            #pragma unroll
            for (int njp = 0; njp < 2; njp++) {
                int row = wn + njp * 16 + ((g >> 1) << 3) + rin;
                uint32_t t[4];
                ldm_x4(t, sB + sw128((row << 7) + k16 * 32 + ((g & 1) << 4)));
                bf[njp * 2][0]     = t[0]; bf[njp * 2][1]     = t[1];
                bf[njp * 2 + 1][0] = t[2]; bf[njp * 2 + 1][1] = t[3];
            }
            #pragma unroll
            for (int mi = 0; mi < MI; mi++)
                #pragma unroll
                for (int nj = 0; nj < 4; nj++)
                    mma16816(acc[mi][nj], af[mi], bf[nj]);
        }
        __syncthreads();
    }

    // ---- epilogue: bias, sumsq, store ----
    float lsq = 0.f;
    const int crow = lane >> 2, ccol = (lane & 3) << 1;
    #pragma unroll
    for (int mi = 0; mi < MI; mi++) {
        #pragma unroll
        for (int nj = 0; nj < 4; nj++) {
            int col  = wn + nj * 8 + ccol;                // within block tile
            float b0 = s_bias[col], b1 = s_bias[col + 1];
            #pragma unroll
            for (int h = 0; h < 2; h++) {                 // h=0: row, h=1: row+8
                int row = row0 + wm + mi * 16 + crow + h * 8;
                float v0 = acc[mi][nj][2 * h]     + b0;
                float v1 = acc[mi][nj][2 * h + 1] + b1;
                lsq += v0 * v0 + v1 * v1;
                if (OUTF32) {
                    *(float2*)(Yf + (size_t)row * ldY + n0 + col) = make_float2(v0, v1);
                } else {
                    *(__nv_bfloat162*)((__nv_bfloat16*)Yb + (size_t)row * ldY + n0 + col) =
                        __floats2bfloat162_rn(v0, v1);
                }
            }
        }
    }
    #pragma unroll
    for (int off = 16; off; off >>= 1)
        lsq += __shfl_xor_sync(0xffffffff, lsq, off);
    if (lane == 0)
        atomicAdd(&g_sumsq[(slot_out << 2) + ((n0 + wn) >> 6)], lsq);
}

// ---------------- finalize ----------------------------------------------------
__global__ void finalize_kernel(float* __restrict__ out) {
    float s = rsqrtf(g_sumsq[16]);
    int i = blockIdx.x * 256 + threadIdx.x;                // 4,194,304 float4
    float4* o = (float4*)out;
    float4 v = o[i];
    v.x *= s; v.y *= s; v.z *= s; v.w *= s;
    o[i] = v;
}

// ---------------- launch ------------------------------------------------------
extern "C" void kernel_launch(void* const* d_in, const int* in_sizes, int n_in,
                              void* d_out, int out_size)
{
    const float* x     = (const float*)d_in[0];
    const float* W_in  = (const float*)d_in[1];
    const float* b_in  = (const float*)d_in[2];
    const float* W_mid = (const float*)d_in[3];
    const float* b_mid = (const float*)d_in[4];
    const float* W_out = (const float*)d_in[5];
    const float* b_out = (const float*)d_in[6];
    float* out = (float*)d_out;

    const int SM_L1  = 1 * (128 * 128 + 128 * 128);        // 32 KB (K=64: 1 stage)
    const int SM_MID = 2 * (128 * 128 + 128 * 128);        // 64 KB
    const int SM_OUT = 2 * (128 * 128 + 64 * 128);         // 48 KB
    cudaFuncSetAttribute(mma_gemm<64, 128, false>,
                         cudaFuncAttributeMaxDynamicSharedMemorySize, SM_L1);
    cudaFuncSetAttribute(mma_gemm<256, 128, false>,
                         cudaFuncAttributeMaxDynamicSharedMemorySize, SM_MID);
    cudaFuncSetAttribute(mma_gemm<256, 64, true>,
                         cudaFuncAttributeMaxDynamicSharedMemorySize, SM_OUT);

    zero_kernel<<<1, 32>>>();
    convert_x<<<16384, 256>>>(x);

    // layer 1: g_xb [B,64] -> g_hb0 (bf16), sumsq slot 0
    prep_in<<<64, 256>>>(W_in, b_in);
    mma_gemm<64, 128, false><<<dim3(2048, 2), 256, SM_L1>>>(0, 1, nullptr, 256, 0);

    // 3 mid transitions (norm scalars folded into weights by prep)
    int a = 1;                                             // 1 = g_hb0, 2 = g_hb1
    for (int l = 0; l < 3; l++) {
        prep_mid<<<256, 256>>>(W_mid, b_mid, l, l);
        mma_gemm<256, 128, false><<<dim3(2048, 2), 256, SM_MID>>>(a, 3 - a, nullptr, 256, l + 1);
        a = 3 - a;
    }

    // out layer -> d_out raw fp32 (slot 4 = g_sumsq[16]), then normalize
    prep_out<<<64, 256>>>(W_out, b_out, 3);
    mma_gemm<256, 64, true><<<dim3(2048, 1), 256, SM_OUT>>>(a, 0, out, 64, 4);
    finalize_kernel<<<16384, 256>>>(out);
}